// round 2
// baseline (speedup 1.0000x reference)
#include <cuda_runtime.h>
#include <math.h>

#define N_  32
#define C_  256
#define H_  56
#define W_  56
#define HW_ 3136          // 56*56
#define C5_ 1280          // C*5

// Scratch (allocation-free rule: __device__ globals)
__device__ float g_buf [N_ * C_ * HW_];   // gelu(relu(x)) : ~103 MB
__device__ float t6_buf[N_ * C_ * C5_];   // gated correlation : ~42 MB

__device__ __forceinline__ float gelu_relu(float v) {
    float t = fmaxf(v, 0.0f);
    // exact GELU (erf form), matching jax.nn.gelu(approximate=False)
    return 0.5f * t * (1.0f + erff(t * 0.7071067811865476f));
}

// ---------------------------------------------------------------------------
// Kernel 1: g = gelu(relu(x)), vectorized float4. Element count divisible by 4.
// ---------------------------------------------------------------------------
__global__ void k_gelu(const float* __restrict__ x) {
    int i = blockIdx.x * blockDim.x + threadIdx.x;
    const float4* x4 = reinterpret_cast<const float4*>(x);
    float4*       g4 = reinterpret_cast<float4*>(g_buf);
    float4 v = x4[i];
    float4 r;
    r.x = gelu_relu(v.x);
    r.y = gelu_relu(v.y);
    r.z = gelu_relu(v.z);
    r.w = gelu_relu(v.w);
    g4[i] = r;
}

// ---------------------------------------------------------------------------
// Kernel 2 (GEMM1 + gate): t6[n,c,r] = p6w[c,r] * (1/56) * sum_i x[n,c,i]*B[r,i]
// B[r,i] = x[n, r/5, h*56 + (w + 2*(r%5) - 4)]  (zero outside width row)
// Tiles: BM=BN=128, BK=16, 256 threads, 8x8 per-thread microtile.
// M=256, N=1280, K=3136 are all exact multiples -> no bounds checks in mainloop.
// ---------------------------------------------------------------------------
__global__ __launch_bounds__(256) void k_corr(const float* __restrict__ x,
                                              const float* __restrict__ p6w) {
    __shared__ float As[16][128];
    __shared__ float Bs[16][128];

    const int n  = blockIdx.z;
    const int m0 = blockIdx.y * 128;   // c tile
    const int r0 = blockIdx.x * 128;   // (c',k) tile
    const float* xb = x + (size_t)n * C_ * HW_;

    const int tid = threadIdx.x;
    const int ty  = tid >> 4;          // 0..15
    const int tx  = tid & 15;          // 0..15

    // A-load mapping: 128 rows x 16 cols, float4 along K, two row phases
    const int a_row = tid >> 2;        // 0..63
    const int a_c4  = (tid & 3) * 4;   // 0,4,8,12

    // B-load mapping: 128 rows x 16 cols, 8 scalars per thread (shift logic)
    const int b_row = tid >> 1;        // 0..127
    const int b_c0  = (tid & 1) * 8;   // 0 or 8
    const int r     = r0 + b_row;
    const int cp    = r / 5;
    const int k5    = r - cp * 5;
    const int shift = 2 * k5 - 4;      // -4,-2,0,2,4
    const float* xrow = xb + (size_t)cp * HW_;

    float acc[8][8];
#pragma unroll
    for (int i = 0; i < 8; ++i)
#pragma unroll
        for (int j = 0; j < 8; ++j) acc[i][j] = 0.0f;

    for (int k0 = 0; k0 < HW_; k0 += 16) {
        // --- load A tile (transposed into As[k][m]) ---
#pragma unroll
        for (int ph = 0; ph < 2; ++ph) {
            int row = a_row + 64 * ph;
            float4 v = *reinterpret_cast<const float4*>(
                xb + (size_t)(m0 + row) * HW_ + k0 + a_c4);
            As[a_c4 + 0][row] = v.x;
            As[a_c4 + 1][row] = v.y;
            As[a_c4 + 2][row] = v.z;
            As[a_c4 + 3][row] = v.w;
        }
        // --- load B tile with horizontal dilated shift ---
        {
            int w0 = (k0 + b_c0) % 56;
#pragma unroll
            for (int j = 0; j < 8; ++j) {
                int w = w0 + j;
                if (w >= 56) w -= 56;
                int ws  = w + shift;
                int col = k0 + b_c0 + j;
                float val = (ws >= 0 && ws < 56) ? xrow[col + shift] : 0.0f;
                Bs[b_c0 + j][b_row] = val;
            }
        }
        __syncthreads();

#pragma unroll
        for (int kk = 0; kk < 16; ++kk) {
            float a[8], b[8];
#pragma unroll
            for (int i = 0; i < 8; ++i) a[i] = As[kk][ty * 8 + i];
#pragma unroll
            for (int j = 0; j < 8; ++j) b[j] = Bs[kk][tx * 8 + j];
#pragma unroll
            for (int i = 0; i < 8; ++i)
#pragma unroll
                for (int j = 0; j < 8; ++j)
                    acc[i][j] = fmaf(a[i], b[j], acc[i][j]);
        }
        __syncthreads();
    }

    // epilogue: scale by 1/sqrt(HW)=1/56 and gate by p6w
    const float s = 1.0f / 56.0f;
    float* t6b = t6_buf + (size_t)n * C_ * C5_;
#pragma unroll
    for (int i = 0; i < 8; ++i) {
        int c = m0 + ty * 8 + i;
#pragma unroll
        for (int j = 0; j < 8; ++j) {
            int rr = r0 + tx * 8 + j;
            t6b[(size_t)c * C5_ + rr] = acc[i][j] * s * __ldg(&p6w[c * C5_ + rr]);
        }
    }
}

// ---------------------------------------------------------------------------
// Kernel 3 (GEMM2): out[n,c,i] = (1/sqrt(1280)) * sum_r t6[n,c,r] * B[r,i]
// B[r,i] = g[n, r/5, i + 56*((r%5)-2)]  (zero outside height range)
// M=256, N=3136 (25 tiles, last partial), K=1280.
// ---------------------------------------------------------------------------
__global__ __launch_bounds__(256) void k_out(float* __restrict__ out) {
    __shared__ float As[16][128];
    __shared__ float Bs[16][128];

    const int n  = blockIdx.z;
    const int m0 = blockIdx.y * 128;   // c tile
    const int n0 = blockIdx.x * 128;   // spatial tile
    const float* Ab = t6_buf + (size_t)n * C_ * C5_;
    const float* gb = g_buf  + (size_t)n * C_ * HW_;

    const int tid = threadIdx.x;
    const int ty  = tid >> 4;
    const int tx  = tid & 15;

    const int a_row = tid >> 2;
    const int a_c4  = (tid & 3) * 4;

    const int b_r = tid >> 4;          // 0..15 (K rows)
    const int b_i = (tid & 15) * 8;    // 0..120 (N cols)

    float acc[8][8];
#pragma unroll
    for (int i = 0; i < 8; ++i)
#pragma unroll
        for (int j = 0; j < 8; ++j) acc[i][j] = 0.0f;

    for (int k0 = 0; k0 < C5_; k0 += 16) {
        // --- load A tile (t6, transposed) ---
#pragma unroll
        for (int ph = 0; ph < 2; ++ph) {
            int row = a_row + 64 * ph;
            float4 v = *reinterpret_cast<const float4*>(
                Ab + (size_t)(m0 + row) * C5_ + k0 + a_c4);
            As[a_c4 + 0][row] = v.x;
            As[a_c4 + 1][row] = v.y;
            As[a_c4 + 2][row] = v.z;
            As[a_c4 + 3][row] = v.w;
        }
        // --- load B tile: vertical-shifted g, float4, uniform-group validity ---
        {
            int rr  = k0 + b_r;
            int cp  = rr / 5;
            int k5  = rr - cp * 5;
            int vsh = 56 * (k5 - 2);   // multiple of 4 -> float4 groups uniform
            const float* grow = gb + (size_t)cp * HW_;
#pragma unroll
            for (int q = 0; q < 2; ++q) {
                int icol = n0 + b_i + q * 4;
                int gi   = icol + vsh;
                float4 v = make_float4(0.f, 0.f, 0.f, 0.f);
                if (icol < HW_ && gi >= 0 && gi < HW_)
                    v = *reinterpret_cast<const float4*>(grow + gi);
                *reinterpret_cast<float4*>(&Bs[b_r][b_i + q * 4]) = v;
            }
        }
        __syncthreads();

#pragma unroll
        for (int kk = 0; kk < 16; ++kk) {
            float a[8], b[8];
#pragma unroll
            for (int i = 0; i < 8; ++i) a[i] = As[kk][ty * 8 + i];
#pragma unroll
            for (int j = 0; j < 8; ++j) b[j] = Bs[kk][tx * 8 + j];
#pragma unroll
            for (int i = 0; i < 8; ++i)
#pragma unroll
                for (int j = 0; j < 8; ++j)
                    acc[i][j] = fmaf(a[i], b[j], acc[i][j]);
        }
        __syncthreads();
    }

    const float s = 0.02795084971874737f;  // 1/sqrt(1280)
    float* ob = out + (size_t)n * C_ * HW_;
#pragma unroll
    for (int i = 0; i < 8; ++i) {
        int c = m0 + ty * 8 + i;
#pragma unroll
        for (int j = 0; j < 8; ++j) {
            int icol = n0 + tx * 8 + j;
            if (icol < HW_)
                ob[(size_t)c * HW_ + icol] = acc[i][j] * s;
        }
    }
}

// ---------------------------------------------------------------------------
extern "C" void kernel_launch(void* const* d_in, const int* in_sizes, int n_in,
                              void* d_out, int out_size) {
    const float* x   = (const float*)d_in[0];   // [32,256,56,56]
    const float* p6w = (const float*)d_in[1];   // [1,256,256,5]
    float* out = (float*)d_out;

    // 1) g = gelu(relu(x))
    int n4 = (N_ * C_ * HW_) / 4;               // divisible by 4
    k_gelu<<<n4 / 256, 256>>>(x);

    // 2) gated correlation t6
    dim3 g1(C5_ / 128, C_ / 128, N_);           // (10, 2, 32)
    k_corr<<<g1, 256>>>(x, p6w);

    // 3) output GEMM
    dim3 g2((HW_ + 127) / 128, C_ / 128, N_);   // (25, 2, 32)
    k_out<<<g2, 256>>>(out);
}

// round 5
// speedup vs baseline: 2.5533x; 2.5533x over previous
#include <cuda_runtime.h>
#include <cuda_bf16.h>
#include <cstdint>
#include <math.h>

#define N_  32
#define C_  256
#define HW_ 3136          // 56*56
#define C5_ 1280          // C*5

// Scratch (allocation-free rule: __device__ globals)
__device__ float g_buf [N_ * C_ * HW_];   // gelu(relu(x))
__device__ float t6_buf[N_ * C_ * C5_];   // gated correlation

// ===========================================================================
// Helpers — plain sm_80+ PTX only (toolchain lowers via compute_100, no 'a')
// ===========================================================================
__device__ __forceinline__ uint32_t smem_u32(const void* p) {
    uint32_t a;
    asm("{ .reg .u64 t; cvta.to.shared.u64 t, %1; cvt.u32.u64 %0, t; }"
        : "=r"(a) : "l"(p));
    return a;
}

__device__ __forceinline__ void ldsm_x4(uint32_t* r, uint32_t a) {
    asm volatile("ldmatrix.sync.aligned.m8n8.x4.shared.b16 {%0,%1,%2,%3}, [%4];"
                 : "=r"(r[0]), "=r"(r[1]), "=r"(r[2]), "=r"(r[3]) : "r"(a));
}
__device__ __forceinline__ void ldsm_x2(uint32_t* r, uint32_t a) {
    asm volatile("ldmatrix.sync.aligned.m8n8.x2.shared.b16 {%0,%1}, [%2];"
                 : "=r"(r[0]), "=r"(r[1]) : "r"(a));
}
__device__ __forceinline__ void mma16816(float* d, const uint32_t* a, const uint32_t* b) {
    asm volatile(
        "mma.sync.aligned.m16n8k16.row.col.f32.bf16.bf16.f32 "
        "{%0,%1,%2,%3}, {%4,%5,%6,%7}, {%8,%9}, {%0,%1,%2,%3};"
        : "+f"(d[0]), "+f"(d[1]), "+f"(d[2]), "+f"(d[3])
        : "r"(a[0]), "r"(a[1]), "r"(a[2]), "r"(a[3]), "r"(b[0]), "r"(b[1]));
}

// Split 8 fp32 into bf16 hi/lo, store 16B each into SW64-swizzled smem.
// Tile rows are 32 bf16 = 64B; swizzle XORs 16B-unit index with (row>>1)&3.
__device__ __forceinline__ void split_store8(char* hi, char* lo, int row, int c0,
                                             const float* f) {
    uint32_t off = (uint32_t)(row * 64 + c0 * 2);
    off ^= (off >> 3) & 0x30;
    uint4 vh, vl;
#define SPLIT_PAIR(a, b, OH, OL) { \
    uint32_t h_; \
    asm("cvt.rn.bf16x2.f32 %0, %1, %2;" : "=r"(h_) : "f"(b), "f"(a)); \
    float rh0 = __uint_as_float(h_ << 16); \
    float rh1 = __uint_as_float(h_ & 0xffff0000u); \
    float r0 = (a) - rh0, r1 = (b) - rh1; \
    uint32_t l_; \
    asm("cvt.rn.bf16x2.f32 %0, %1, %2;" : "=r"(l_) : "f"(r1), "f"(r0)); \
    OH = h_; OL = l_; }
    SPLIT_PAIR(f[0], f[1], vh.x, vl.x)
    SPLIT_PAIR(f[2], f[3], vh.y, vl.y)
    SPLIT_PAIR(f[4], f[5], vh.z, vl.z)
    SPLIT_PAIR(f[6], f[7], vh.w, vl.w)
#undef SPLIT_PAIR
    *reinterpret_cast<uint4*>(hi + off) = vh;
    *reinterpret_cast<uint4*>(lo + off) = vl;
}

// Warp-level compute of one BK=32 chunk from one smem buffer.
// Buffer layout: Ah @0, Al @8192, Bh @16384, Bl @24576 (bytes).
__device__ __forceinline__ void compute_chunk(uint32_t sb, int l, int wm, int wn,
                                              float acc[4][4][4]) {
#pragma unroll
    for (int kk = 0; kk < 2; ++kk) {
        uint32_t ah[4][4], al[4][4];
#pragma unroll
        for (int t = 0; t < 4; ++t) {
            int m = wm * 64 + t * 16 + (l & 15);
            uint32_t off = (uint32_t)(m * 64 + (kk * 2 + (l >> 4)) * 16);
            off ^= (off >> 3) & 0x30;
            ldsm_x4(ah[t], sb + off);
            ldsm_x4(al[t], sb + 8192 + off);
        }
        uint32_t bh[4][2], bl[4][2];
#pragma unroll
        for (int u = 0; u < 4; ++u) {
            int nr = wn * 32 + u * 8 + (l & 7);
            uint32_t off = (uint32_t)(nr * 64 + (kk * 2 + ((l >> 3) & 1)) * 16);
            off ^= (off >> 3) & 0x30;
            ldsm_x2(bh[u], sb + 16384 + off);
            ldsm_x2(bl[u], sb + 24576 + off);
        }
#pragma unroll
        for (int t = 0; t < 4; ++t)
#pragma unroll
            for (int u = 0; u < 4; ++u) {
                mma16816(acc[t][u], ah[t], bh[u]);
                mma16816(acc[t][u], ah[t], bl[u]);
                mma16816(acc[t][u], al[t], bh[u]);
            }
    }
}

__device__ __forceinline__ float gelu_relu(float v) {
    float t = fmaxf(v, 0.0f);
    return 0.5f * t * (1.0f + erff(t * 0.7071067811865476f));
}

// ---------------------------------------------------------------------------
// Kernel 1: g = gelu(relu(x))
// ---------------------------------------------------------------------------
__global__ void k_gelu(const float* __restrict__ x) {
    int i = blockIdx.x * blockDim.x + threadIdx.x;
    const float4* x4 = reinterpret_cast<const float4*>(x);
    float4*       g4 = reinterpret_cast<float4*>(g_buf);
    float4 v = x4[i];
    float4 r;
    r.x = gelu_relu(v.x); r.y = gelu_relu(v.y);
    r.z = gelu_relu(v.z); r.w = gelu_relu(v.w);
    g4[i] = r;
}

#define SMEM_BYTES 65536   // 2 buffers x 32KB

// ---------------------------------------------------------------------------
// GEMM1: t6[n,c,r] = p6w[c,r]*(1/56)*sum_i x[n,c,i]*x[n,r/5, i+shift(r%5)]
// M=128 (c), N=128 (r), K=3136 in 98 chunks of 32.
// ---------------------------------------------------------------------------
__global__ __launch_bounds__(256) void k_mma1(const float* __restrict__ x,
                                              const float* __restrict__ p6w) {
    extern __shared__ __align__(128) char smem[];
    const uint32_t sbase = smem_u32(smem);
    const int tid = threadIdx.x;
    const int l = tid & 31, wid = tid >> 5;
    const int wm = wid >> 2, wn = wid & 3;
    const int n = blockIdx.z, m0 = blockIdx.y * 128, r0 = blockIdx.x * 128;
    const float* xb = x + (size_t)n * C_ * HW_;

    const int brow = tid >> 1;           // 0..127 (tile row for A and B builds)
    const int cb   = (tid & 1) * 16;     // 0 or 16
    const float* arow = xb + (size_t)(m0 + brow) * HW_;
    const int r = r0 + brow, cp = r / 5;
    const int shift = 2 * (r - cp * 5) - 4;
    const float* brp = xb + (size_t)cp * HW_;

    float acc[4][4][4];
#pragma unroll
    for (int t = 0; t < 4; ++t)
#pragma unroll
        for (int u = 0; u < 4; ++u)
#pragma unroll
            for (int q = 0; q < 4; ++q) acc[t][u][q] = 0.0f;

    float areg[16], breg[16];
    auto loadch = [&](int it) {
        const int kc0 = it * 32;
        *reinterpret_cast<float4*>(areg + 0)  = *reinterpret_cast<const float4*>(arow + kc0 + cb + 0);
        *reinterpret_cast<float4*>(areg + 4)  = *reinterpret_cast<const float4*>(arow + kc0 + cb + 4);
        *reinterpret_cast<float4*>(areg + 8)  = *reinterpret_cast<const float4*>(arow + kc0 + cb + 8);
        *reinterpret_cast<float4*>(areg + 12) = *reinterpret_cast<const float4*>(arow + kc0 + cb + 12);
        int w0 = (kc0 + cb) % 56;
#pragma unroll
        for (int e = 0; e < 16; ++e) {
            int w = w0 + e;
            if (w >= 56) w -= 56;
            int ws = w + shift;
            breg[e] = (ws >= 0 && ws < 56) ? brp[kc0 + cb + e + shift] : 0.0f;
        }
    };

    loadch(0);
    const int NCH = HW_ / 32;  // 98
    for (int it = 0; it < NCH; ++it) {
        char* base = smem + (it & 1) * 32768;
        split_store8(base,         base + 8192,  brow, cb,     areg);
        split_store8(base,         base + 8192,  brow, cb + 8, areg + 8);
        split_store8(base + 16384, base + 24576, brow, cb,     breg);
        split_store8(base + 16384, base + 24576, brow, cb + 8, breg + 8);
        __syncthreads();
        if (it + 1 < NCH) loadch(it + 1);
        compute_chunk(sbase + (it & 1) * 32768, l, wm, wn, acc);
    }

    // epilogue: scale 1/56, gate by p6w
    const float s = 1.0f / 56.0f;
    float* t6b = t6_buf + (size_t)n * C_ * C5_;
#pragma unroll
    for (int t = 0; t < 4; ++t) {
        int mrow = wm * 64 + t * 16 + (l >> 2);
        int c0 = m0 + mrow, c1 = c0 + 8;
#pragma unroll
        for (int u = 0; u < 4; ++u) {
            int col = r0 + wn * 32 + u * 8 + 2 * (l & 3);
            float2 pw0 = *reinterpret_cast<const float2*>(p6w + (size_t)c0 * C5_ + col);
            float2 pw1 = *reinterpret_cast<const float2*>(p6w + (size_t)c1 * C5_ + col);
            float2 o0 = make_float2(acc[t][u][0] * s * pw0.x, acc[t][u][1] * s * pw0.y);
            float2 o1 = make_float2(acc[t][u][2] * s * pw1.x, acc[t][u][3] * s * pw1.y);
            *reinterpret_cast<float2*>(t6b + (size_t)c0 * C5_ + col) = o0;
            *reinterpret_cast<float2*>(t6b + (size_t)c1 * C5_ + col) = o1;
        }
    }
}

// ---------------------------------------------------------------------------
// GEMM2: out[n,c,i] = (1/sqrt(1280)) * sum_r t6[n,c,r] * g[n, r/5, i+56*((r%5)-2)]
// M=128 (c), N=128 (i; last tile partial), K=1280 in 40 chunks of 32.
// ---------------------------------------------------------------------------
__global__ __launch_bounds__(256) void k_mma2(float* __restrict__ out) {
    extern __shared__ __align__(128) char smem[];
    const uint32_t sbase = smem_u32(smem);
    const int tid = threadIdx.x;
    const int l = tid & 31, wid = tid >> 5;
    const int wm = wid >> 2, wn = wid & 3;
    const int n = blockIdx.z, m0 = blockIdx.y * 128, n0 = blockIdx.x * 128;
    const float* Ab = t6_buf + (size_t)n * C_ * C5_;
    const float* gb = g_buf  + (size_t)n * C_ * HW_;

    const int brow = tid >> 1;
    const int cb   = (tid & 1) * 16;
    const float* arow = Ab + (size_t)(m0 + brow) * C5_;
    const int i_sp = n0 + brow;
    const bool vi  = (i_sp < HW_);

    float acc[4][4][4];
#pragma unroll
    for (int t = 0; t < 4; ++t)
#pragma unroll
        for (int u = 0; u < 4; ++u)
#pragma unroll
            for (int q = 0; q < 4; ++q) acc[t][u][q] = 0.0f;

    float areg[16], breg[16];
    auto loadch = [&](int it) {
        const int kc0 = it * 32;
        *reinterpret_cast<float4*>(areg + 0)  = *reinterpret_cast<const float4*>(arow + kc0 + cb + 0);
        *reinterpret_cast<float4*>(areg + 4)  = *reinterpret_cast<const float4*>(arow + kc0 + cb + 4);
        *reinterpret_cast<float4*>(areg + 8)  = *reinterpret_cast<const float4*>(arow + kc0 + cb + 8);
        *reinterpret_cast<float4*>(areg + 12) = *reinterpret_cast<const float4*>(arow + kc0 + cb + 12);
#pragma unroll
        for (int e = 0; e < 16; ++e) {
            int rr = kc0 + cb + e;
            int cp = rr / 5;
            int k5 = rr - 5 * cp;
            int gi = i_sp + 56 * (k5 - 2);
            breg[e] = (vi && gi >= 0 && gi < HW_) ? gb[(size_t)cp * HW_ + gi] : 0.0f;
        }
    };

    loadch(0);
    const int NCH = C5_ / 32;  // 40
    for (int it = 0; it < NCH; ++it) {
        char* base = smem + (it & 1) * 32768;
        split_store8(base,         base + 8192,  brow, cb,     areg);
        split_store8(base,         base + 8192,  brow, cb + 8, areg + 8);
        split_store8(base + 16384, base + 24576, brow, cb,     breg);
        split_store8(base + 16384, base + 24576, brow, cb + 8, breg + 8);
        __syncthreads();
        if (it + 1 < NCH) loadch(it + 1);
        compute_chunk(sbase + (it & 1) * 32768, l, wm, wn, acc);
    }

    const float s = 0.02795084971874737f;  // 1/sqrt(1280)
    float* ob = out + (size_t)n * C_ * HW_;
#pragma unroll
    for (int t = 0; t < 4; ++t) {
        int mrow = wm * 64 + t * 16 + (l >> 2);
        int c0 = m0 + mrow, c1 = c0 + 8;
#pragma unroll
        for (int u = 0; u < 4; ++u) {
            int col = n0 + wn * 32 + u * 8 + 2 * (l & 3);
            if (col < HW_) {
                float2 o0 = make_float2(acc[t][u][0] * s, acc[t][u][1] * s);
                float2 o1 = make_float2(acc[t][u][2] * s, acc[t][u][3] * s);
                *reinterpret_cast<float2*>(ob + (size_t)c0 * HW_ + col) = o0;
                *reinterpret_cast<float2*>(ob + (size_t)c1 * HW_ + col) = o1;
            }
        }
    }
}

// ---------------------------------------------------------------------------
extern "C" void kernel_launch(void* const* d_in, const int* in_sizes, int n_in,
                              void* d_out, int out_size) {
    const float* x   = (const float*)d_in[0];   // [32,256,56,56]
    const float* p6w = (const float*)d_in[1];   // [1,256,256,5]
    float* out = (float*)d_out;

    cudaFuncSetAttribute(k_mma1, cudaFuncAttributeMaxDynamicSharedMemorySize, SMEM_BYTES);
    cudaFuncSetAttribute(k_mma2, cudaFuncAttributeMaxDynamicSharedMemorySize, SMEM_BYTES);

    int n4 = (N_ * C_ * HW_) / 4;
    k_gelu<<<n4 / 256, 256>>>(x);

    dim3 g1(C5_ / 128, C_ / 128, N_);           // (10, 2, 32)
    k_mma1<<<g1, 256, SMEM_BYTES>>>(x, p6w);

    dim3 g2((HW_ + 127) / 128, C_ / 128, N_);   // (25, 2, 32)
    k_mma2<<<g2, 256, SMEM_BYTES>>>(out);
}